// round 3
// baseline (speedup 1.0000x reference)
#include <cuda_runtime.h>

#define B 128
#define DF 2048
#define KSPLIT 32
#define KCHUNK 64           // DF / KSPLIT
#define NBLOCKS 128
#define NTHREADS 256

// Scratch (static device globals; no allocation).
__device__ float g_Gp[KSPLIT * B * B];   // split-K partial Gram
__device__ float g_G[B * B];             // reduced Gram
__device__ float g_part[NBLOCKS];        // per-block loss partials
__device__ unsigned g_bar[2];            // monotonic barrier counters (never reset)
__device__ unsigned g_fin;               // monotonic finalize counter (never reset)

// Monotonic grid barrier: no reset across graph replays (2^32 % 128 == 0).
__device__ __forceinline__ void grid_barrier(int which) {
    __syncthreads();
    if (threadIdx.x == 0) {
        __threadfence();                                   // release
        unsigned old = atomicAdd(&g_bar[which], 1u);
        unsigned target = old - (old & (NBLOCKS - 1u)) + NBLOCKS;
        while ((int)(*(volatile unsigned*)&g_bar[which] - target) < 0) { }
        __threadfence();                                   // acquire
    }
    __syncthreads();
}

__global__ __launch_bounds__(NTHREADS) void fused_angle_loss(
    const float* __restrict__ X, float* __restrict__ out) {

    __shared__ float smemBuf[2 * KCHUNK * 68];   // 34.8KB, reused across phases
    const int b = blockIdx.x;
    const int t = threadIdx.x;

    // ============================ Phase 1: split-K Gram =====================
    // block b: z = b>>2 (K chunk), tile index b&3 -> 64x64 output tile.
    {
        const int z     = b >> 2;
        const int tileR = ((b >> 1) & 1) * 64;
        const int tileC = (b & 1) * 64;
        const int kBase = z * KCHUNK;

        float (*As)[68] = (float(*)[68])smemBuf;
        float (*Bs)[68] = (float(*)[68])(smemBuf + KCHUNK * 68);

        const int lr = t >> 2;            // 0..63 row within tile
        const int c4 = (t & 3) * 4;       // k sub-offset
#pragma unroll
        for (int i = 0; i < 4; i++) {
            const int k0 = c4 + 16 * i;
            float4 va = *(const float4*)(X + (size_t)(tileR + lr) * DF + kBase + k0);
            As[k0 + 0][lr] = va.x; As[k0 + 1][lr] = va.y;
            As[k0 + 2][lr] = va.z; As[k0 + 3][lr] = va.w;
            float4 vb = *(const float4*)(X + (size_t)(tileC + lr) * DF + kBase + k0);
            Bs[k0 + 0][lr] = vb.x; Bs[k0 + 1][lr] = vb.y;
            Bs[k0 + 2][lr] = vb.z; Bs[k0 + 3][lr] = vb.w;
        }
        __syncthreads();

        const int r0 = (t >> 4) * 4;
        const int c0 = (t & 15) * 4;
        float acc[4][4] = {};
#pragma unroll 16
        for (int k = 0; k < KCHUNK; k++) {
            float4 a  = *(const float4*)&As[k][r0];
            float4 bb = *(const float4*)&Bs[k][c0];
            const float av[4] = {a.x, a.y, a.z, a.w};
            const float bv[4] = {bb.x, bb.y, bb.z, bb.w};
#pragma unroll
            for (int ii = 0; ii < 4; ii++)
#pragma unroll
                for (int jj = 0; jj < 4; jj++)
                    acc[ii][jj] = fmaf(av[ii], bv[jj], acc[ii][jj]);
        }

        float* dst = g_Gp + (size_t)z * (B * B);
#pragma unroll
        for (int ii = 0; ii < 4; ii++) {
            float4 v = make_float4(acc[ii][0], acc[ii][1], acc[ii][2], acc[ii][3]);
            *(float4*)&dst[(tileR + r0 + ii) * B + tileC + c0] = v;
        }
    }

    grid_barrier(0);

    // ===================== Phase 2: split-K reduce (all 128 blocks) =========
    // 4096 float4 outputs / 128 blocks = 32 per block, one per thread (t<32).
    if (t < 32) {
        const int f4 = b * 32 + t;
        const float4* src = (const float4*)g_Gp;
        float4 s = make_float4(0.f, 0.f, 0.f, 0.f);
#pragma unroll
        for (int z = 0; z < KSPLIT; z++) {
            float4 v = __ldcg(src + (size_t)z * 4096 + f4);
            s.x += v.x; s.y += v.y; s.z += v.z; s.w += v.w;
        }
        ((float4*)g_G)[f4] = s;
    }

    grid_barrier(1);

    // ======================= Phase 3: loss (all 128 blocks) =================
    // b = group*8 + slice. Group g=(target,sub); slice s picks pair row
    // r = s: pairs (j0,j1) = (16p+s, 16p+s+8) for the 7 p != target.
    {
        const int g    = b >> 3;
        const int s    = b & 7;
        const int tgt  = g >> 1;
        const int sb   = g & 1;
        const int base = tgt * 16 + sb * 8;
        const int k    = t & 127;
        const int h    = t >> 7;

        float* sS   = smemBuf;          // [128]
        float* sInv = smemBuf + 128;    // [128]
        float* red  = smemBuf + 256;    // [8]

        if (h == 0) {
            float sk = 0.f;
#pragma unroll
            for (int i = 0; i < 8; i++) sk += __ldcg(&g_G[(base + i) * B + k]);
            sS[k] = sk * 0.125f;
        }
        __syncthreads();

        float q = 0.f;
#pragma unroll
        for (int i = 0; i < 8; i++) q += sS[base + i];
        q *= 0.125f;

        if (h == 0) {
            const float n2 = __ldcg(&g_G[k * B + k]) - 2.f * sS[k] + q;
            const float nr = sqrtf(fmaxf(n2, 0.f));
            sInv[k] = 1.f / fmaxf(nr, 1e-12f);
        }
        __syncthreads();

        const float sk   = sS[k];
        const float invk = sInv[k];
        float acc = 0.f;
        // h==0 handles p in [0,4), h==1 handles p in [4,8).
#pragma unroll
        for (int pi = 0; pi < 4; pi++) {
            const int p = h * 4 + pi;
            if (p == tgt) continue;
            const int j0 = p * 16 + s;
            const int j1 = j0 + 8;
            const float a0 = (__ldcg(&g_G[j0 * B + k]) - sS[j0] - sk + q) * (sInv[j0] * invk);
            const float a1 = (__ldcg(&g_G[j1 * B + k]) - sS[j1] - sk + q) * (sInv[j1] * invk);
            acc += fabsf(a0 - a1);
        }

        // Deterministic block reduction over 256 threads.
#pragma unroll
        for (int o = 16; o > 0; o >>= 1) acc += __shfl_down_sync(0xffffffffu, acc, o);
        if ((t & 31) == 0) red[t >> 5] = acc;
        __syncthreads();

        if (t == 0) {
            float sum = 0.f;
#pragma unroll
            for (int w = 0; w < 8; w++) sum += red[w];
            g_part[b] = sum;
            __threadfence();
            unsigned old = atomicAdd(&g_fin, 1u);
            if ((old & (NBLOCKS - 1u)) == (NBLOCKS - 1u)) {
                // Last block finalizes: fixed-order chains -> deterministic.
                float c0 = 0.f, c1 = 0.f, c2 = 0.f, c3 = 0.f;
#pragma unroll
                for (int i = 0; i < 32; i++) {
                    c0 += __ldcg(&g_part[i]);
                    c1 += __ldcg(&g_part[32 + i]);
                    c2 += __ldcg(&g_part[64 + i]);
                    c3 += __ldcg(&g_part[96 + i]);
                }
                out[0] = ((c0 + c1) + (c2 + c3)) * (1.0f / 114688.0f);
            }
        }
    }
}

extern "C" void kernel_launch(void* const* d_in, const int* in_sizes, int n_in,
                              void* d_out, int out_size) {
    const float* X = (const float*)d_in[0];   // [128, 2048] fp32
    float* out = (float*)d_out;               // scalar loss

    fused_angle_loss<<<NBLOCKS, NTHREADS>>>(X, out);
}

// round 4
// speedup vs baseline: 1.1382x; 1.1382x over previous
#include <cuda_runtime.h>

#define B 128
#define DF 2048
#define KSPLIT 32
#define KCHUNK 64           // DF / KSPLIT
#define NBLOCKS 128
#define NTHREADS 256

// Scratch (static device globals; no allocation).
__device__ float g_Gp[KSPLIT * B * B];   // split-K partial Gram
__device__ float g_G[B * B];             // reduced Gram
__device__ float g_part[NBLOCKS];        // per-block loss partials
__device__ unsigned g_bar[2];            // monotonic barrier counters (never reset)
__device__ unsigned g_fin;               // monotonic finalize counter (never reset)

// Monotonic grid barrier: no reset across graph replays (2^32 % 128 == 0).
__device__ __forceinline__ void grid_barrier(int which) {
    __syncthreads();
    if (threadIdx.x == 0) {
        __threadfence();                                   // release
        unsigned old = atomicAdd(&g_bar[which], 1u);
        unsigned target = old - (old & (NBLOCKS - 1u)) + NBLOCKS;
        while ((int)(*(volatile unsigned*)&g_bar[which] - target) < 0) {
            __nanosleep(64);
        }
        __threadfence();                                   // acquire
    }
    __syncthreads();
}

__global__ __launch_bounds__(NTHREADS) void fused_angle_loss(
    const float* __restrict__ X, float* __restrict__ out) {

    __shared__ float smemBuf[2 * KCHUNK * 68];   // 34.8KB, reused across phases
    const int b = blockIdx.x;
    const int t = threadIdx.x;

    // ============================ Phase 1: split-K Gram =====================
    // block b: z = b>>2 (K chunk), tile index b&3 -> 64x64 output tile.
    {
        const int z     = b >> 2;
        const int tileR = ((b >> 1) & 1) * 64;
        const int tileC = (b & 1) * 64;
        const int kBase = z * KCHUNK;

        float (*As)[68] = (float(*)[68])smemBuf;
        float (*Bs)[68] = (float(*)[68])(smemBuf + KCHUNK * 68);

        const int lr = t >> 2;            // 0..63 row within tile
        const int c4 = (t & 3) * 4;       // k sub-offset
#pragma unroll
        for (int i = 0; i < 4; i++) {
            const int k0 = c4 + 16 * i;
            float4 va = *(const float4*)(X + (size_t)(tileR + lr) * DF + kBase + k0);
            As[k0 + 0][lr] = va.x; As[k0 + 1][lr] = va.y;
            As[k0 + 2][lr] = va.z; As[k0 + 3][lr] = va.w;
            float4 vb = *(const float4*)(X + (size_t)(tileC + lr) * DF + kBase + k0);
            Bs[k0 + 0][lr] = vb.x; Bs[k0 + 1][lr] = vb.y;
            Bs[k0 + 2][lr] = vb.z; Bs[k0 + 3][lr] = vb.w;
        }
        __syncthreads();

        const int r0 = (t >> 4) * 4;
        const int c0 = (t & 15) * 4;
        float acc[4][4] = {};
#pragma unroll 16
        for (int k = 0; k < KCHUNK; k++) {
            float4 a  = *(const float4*)&As[k][r0];
            float4 bb = *(const float4*)&Bs[k][c0];
            const float av[4] = {a.x, a.y, a.z, a.w};
            const float bv[4] = {bb.x, bb.y, bb.z, bb.w};
#pragma unroll
            for (int ii = 0; ii < 4; ii++)
#pragma unroll
                for (int jj = 0; jj < 4; jj++)
                    acc[ii][jj] = fmaf(av[ii], bv[jj], acc[ii][jj]);
        }

        float* dst = g_Gp + (size_t)z * (B * B);
#pragma unroll
        for (int ii = 0; ii < 4; ii++) {
            float4 v = make_float4(acc[ii][0], acc[ii][1], acc[ii][2], acc[ii][3]);
            *(float4*)&dst[(tileR + r0 + ii) * B + tileC + c0] = v;
        }
    }

    grid_barrier(0);

    // ===================== Phase 2: split-K reduce (all 128 blocks) =========
    // 4096 float4 outputs / 128 blocks = 32 per block, one per thread (t<32).
    if (t < 32) {
        const int f4 = b * 32 + t;
        const float4* src = (const float4*)g_Gp;
        float4 s = make_float4(0.f, 0.f, 0.f, 0.f);
#pragma unroll
        for (int z = 0; z < KSPLIT; z++) {
            float4 v = __ldcg(src + (size_t)z * 4096 + f4);
            s.x += v.x; s.y += v.y; s.z += v.z; s.w += v.w;
        }
        ((float4*)g_G)[f4] = s;
    }

    grid_barrier(1);

    // ======================= Phase 3: loss (all 128 blocks) =================
    // b = group*8 + slice. Group g=(target,sub); slice s -> pairs
    // (j0,j1) = (16p+s, 16p+s+8) for the 7 p != target.
    // ALL global loads issued in one batch up front (single L2 round),
    // then compute runs purely out of registers + SMEM.
    {
        const int g    = b >> 3;
        const int s    = b & 7;
        const int tgt  = g >> 1;
        const int sb   = g & 1;
        const int base = tgt * 16 + sb * 8;
        const int k    = t & 127;
        const int h    = t >> 7;

        float* sS    = smemBuf;          // [128] mean row-dot (already /8)
        float* sInv  = smemBuf + 128;    // [128] 1/norm
        float* sDiag = smemBuf + 256;    // [128] G[k][k]
        float* red   = smemBuf + 384;    // [8]
        int*   sFlag = (int*)(smemBuf + 392);

        // ---- batched loads (independent; one MLP window) ----
        float rowv[8];                   // sS partials (h==0) ; unused h==1
        float gv0[4], gv1[4];            // pair G values for p = h*4+pi
        float dia = 0.f;

        if (h == 0) {
#pragma unroll
            for (int i = 0; i < 8; i++) rowv[i] = __ldcg(&g_G[(base + i) * B + k]);
        } else {
            dia = __ldcg(&g_G[k * B + k]);
        }
#pragma unroll
        for (int pi = 0; pi < 4; pi++) {
            const int p = h * 4 + pi;
            const int j0 = p * 16 + s;
            // load even for p==tgt (values unused); keeps the batch uniform
            gv0[pi] = __ldcg(&g_G[j0 * B + k]);
            gv1[pi] = __ldcg(&g_G[(j0 + 8) * B + k]);
        }

        if (h == 0) {
            float sk = ((rowv[0] + rowv[1]) + (rowv[2] + rowv[3]))
                     + ((rowv[4] + rowv[5]) + (rowv[6] + rowv[7]));
            sS[k] = sk * 0.125f;
        } else {
            sDiag[k] = dia;
        }
        __syncthreads();

        float q = 0.f;
#pragma unroll
        for (int i = 0; i < 8; i++) q += sS[base + i];
        q *= 0.125f;

        if (h == 0) {
            const float n2 = sDiag[k] - 2.f * sS[k] + q;
            const float nr = sqrtf(fmaxf(n2, 0.f));
            sInv[k] = 1.f / fmaxf(nr, 1e-12f);
        }
        __syncthreads();

        const float sk   = sS[k];
        const float invk = sInv[k];
        float acc = 0.f;
#pragma unroll
        for (int pi = 0; pi < 4; pi++) {
            const int p = h * 4 + pi;
            if (p == tgt) continue;
            const int j0 = p * 16 + s;
            const int j1 = j0 + 8;
            const float a0 = (gv0[pi] - sS[j0] - sk + q) * (sInv[j0] * invk);
            const float a1 = (gv1[pi] - sS[j1] - sk + q) * (sInv[j1] * invk);
            acc += fabsf(a0 - a1);
        }

        // Deterministic block reduction over 256 threads.
#pragma unroll
        for (int o = 16; o > 0; o >>= 1) acc += __shfl_down_sync(0xffffffffu, acc, o);
        if ((t & 31) == 0) red[t >> 5] = acc;
        __syncthreads();

        if (t == 0) {
            float sum = 0.f;
#pragma unroll
            for (int w = 0; w < 8; w++) sum += red[w];
            g_part[b] = sum;
            __threadfence();
            unsigned old = atomicAdd(&g_fin, 1u);
            sFlag[0] = ((old & (NBLOCKS - 1u)) == (NBLOCKS - 1u)) ? 1 : 0;
        }
        __syncthreads();

        // ---- parallel deterministic finalize by the last-arriving block ----
        if (sFlag[0]) {
            float v = (t < NBLOCKS) ? __ldcg(&g_part[t]) : 0.f;
            // fixed shfl tree within each warp, then fixed-order cross-warp sum
#pragma unroll
            for (int o = 16; o > 0; o >>= 1) v += __shfl_down_sync(0xffffffffu, v, o);
            if ((t & 31) == 0) red[t >> 5] = v;
            __syncthreads();
            if (t == 0) {
                float tot = ((red[0] + red[1]) + (red[2] + red[3]));
                out[0] = tot * (1.0f / 114688.0f);
            }
        }
    }
}

extern "C" void kernel_launch(void* const* d_in, const int* in_sizes, int n_in,
                              void* d_out, int out_size) {
    const float* X = (const float*)d_in[0];   // [128, 2048] fp32
    float* out = (float*)d_out;               // scalar loss

    fused_angle_loss<<<NBLOCKS, NTHREADS>>>(X, out);
}